// round 14
// baseline (speedup 1.0000x reference)
#include <cuda_runtime.h>
#include <cuda_bf16.h>
#include <math.h>
#include <stdint.h>

#define DIM    2048
#define BATCH  16384
#define NLAYERS 4

static __device__ __constant__ float kS[3] = {0.1f, 0.1f, 0.05f};
#define DIVC 0.38f
#define CAPV 10.0f

#if defined(__CUDA_ARCH_FEAT_SM103_ALL) || defined(__CUDA_ARCH_FEAT_SM100_ALL) || defined(__CUDA_ARCH_FEAT_SM101_ALL)
#define HAS_TCGEN05 1
#else
#define HAS_TCGEN05 0
#endif

// ---------------- scratch (static device globals; no allocation) -------------
__device__ __nv_bfloat16 g_hhi[(size_t)BATCH * DIM];
__device__ __nv_bfloat16 g_hlo[(size_t)BATCH * DIM];
__device__ __nv_bfloat16 g_Thi[(size_t)BATCH * DIM];
__device__ __nv_bfloat16 g_Tlo[(size_t)BATCH * DIM];
__device__ __nv_bfloat16 g_W1hi[(size_t)DIM * DIM];
__device__ __nv_bfloat16 g_W1lo[(size_t)DIM * DIM];
__device__ __nv_bfloat16 g_W2hi[(size_t)DIM * DIM];
__device__ __nv_bfloat16 g_W2lo[(size_t)DIM * DIM];
__device__ float g_dirs[3 * DIM];
__device__ float4 g_coef4[BATCH];             // {ce, cc, cn, sc}
__device__ float4 g_part[(size_t)BATCH * 8];  // per (row, N-tile) partial stats

// ---------------- PTX helpers -------------------------------------------------
__device__ __forceinline__ uint32_t smem_u32(const void* p) {
    uint32_t a;
    asm("{ .reg .u64 t; cvta.to.shared.u64 t, %1; cvt.u32.u64 %0, t; }" : "=r"(a) : "l"(p));
    return a;
}

#if HAS_TCGEN05
#define TCGEN05_ALLOC(sm, n) \
    asm volatile("tcgen05.alloc.cta_group::1.sync.aligned.shared::cta.b32 [%0], %1;" :: "r"(sm), "r"(n) : "memory")
#define TCGEN05_RELINQ() \
    asm volatile("tcgen05.relinquish_alloc_permit.cta_group::1.sync.aligned;")
#define TCGEN05_DEALLOC(t, n) \
    asm volatile("tcgen05.dealloc.cta_group::1.sync.aligned.b32 %0, %1;" :: "r"(t), "r"(n))
#define TCGEN05_COMMIT(mb) \
    asm volatile("tcgen05.commit.cta_group::1.mbarrier::arrive::one.shared::cluster.b64 [%0];" :: "r"(mb) : "memory")
#define TCGEN05_FENCE_AFTER() asm volatile("tcgen05.fence::after_thread_sync;" ::: "memory")
#define TCGEN05_WAIT_LD() asm volatile("tcgen05.wait::ld.sync.aligned;" ::: "memory")
#else
#define TCGEN05_ALLOC(sm, n)   ((void)0)
#define TCGEN05_RELINQ()       ((void)0)
#define TCGEN05_DEALLOC(t, n)  ((void)0)
#define TCGEN05_COMMIT(mb)     ((void)0)
#define TCGEN05_FENCE_AFTER()  ((void)0)
#define TCGEN05_WAIT_LD()      ((void)0)
#endif

#define MBARRIER_INIT(mb, c) \
    asm volatile("mbarrier.init.shared.b64 [%0], %1;" :: "r"(mb), "r"(c) : "memory")
#define MBARRIER_INVAL(mb) \
    asm volatile("mbarrier.inval.shared.b64 [%0];" :: "r"(mb) : "memory")
#define FENCE_PROXY_ASYNC() asm volatile("fence.proxy.async.shared::cta;" ::: "memory")
#define CP_ASYNC16(dst, src) \
    asm volatile("cp.async.cg.shared.global [%0], [%1], 16;" :: "r"(dst), "l"(src) : "memory")
#define CP_ASYNC_MBAR_ARRIVE(mb) \
    asm volatile("cp.async.mbarrier.arrive.noinc.shared::cta.b64 [%0];" :: "r"(mb) : "memory")
#define STS128(addr, a, b, c, d) \
    asm volatile("st.shared.v4.b32 [%0], {%1,%2,%3,%4};" :: "r"(addr), "r"(a), "r"(b), "r"(c), "r"(d) : "memory")
#define LDS128(a, b, c, d, addr) \
    asm volatile("ld.shared.v4.b32 {%0,%1,%2,%3}, [%4];" : "=r"(a), "=r"(b), "=r"(c), "=r"(d) : "r"(addr))

__device__ __forceinline__ void mbar_wait(uint32_t mb, uint32_t parity) {
    uint32_t done;
    asm volatile(
        "{\n\t.reg .pred p;\n\t"
        "mbarrier.try_wait.parity.acquire.cta.shared::cta.b64 p, [%1], %2;\n\t"
        "selp.b32 %0, 1, 0, p;\n\t}"
        : "=r"(done) : "r"(mb), "r"(parity) : "memory");
    if (!done) {
        asm volatile(
            "{\n\t.reg .pred P1;\n\t"
            "W_%=:\n\t"
            "mbarrier.try_wait.parity.acquire.cta.shared::cta.b64 P1, [%0], %1, 0x989680;\n\t"
            "@P1 bra.uni D_%=;\n\t"
            "bra.uni W_%=;\n\t"
            "D_%=:\n\t}"
            :: "r"(mb), "r"(parity) : "memory");
    }
}

__device__ __forceinline__ void tcgen05_ld32x32(uint32_t* r, uint32_t addr) {
#if HAS_TCGEN05
    asm volatile(
        "tcgen05.ld.sync.aligned.32x32b.x32.b32 "
        "{%0,%1,%2,%3,%4,%5,%6,%7,%8,%9,%10,%11,%12,%13,%14,%15,"
        "%16,%17,%18,%19,%20,%21,%22,%23,%24,%25,%26,%27,%28,%29,%30,%31}, [%32];"
        : "=r"(r[0]), "=r"(r[1]), "=r"(r[2]), "=r"(r[3]), "=r"(r[4]), "=r"(r[5]), "=r"(r[6]), "=r"(r[7]),
          "=r"(r[8]), "=r"(r[9]), "=r"(r[10]), "=r"(r[11]), "=r"(r[12]), "=r"(r[13]), "=r"(r[14]), "=r"(r[15]),
          "=r"(r[16]), "=r"(r[17]), "=r"(r[18]), "=r"(r[19]), "=r"(r[20]), "=r"(r[21]), "=r"(r[22]), "=r"(r[23]),
          "=r"(r[24]), "=r"(r[25]), "=r"(r[26]), "=r"(r[27]), "=r"(r[28]), "=r"(r[29]), "=r"(r[30]), "=r"(r[31])
        : "r"(addr));
#else
    for (int i = 0; i < 32; i++) r[i] = 0;
#endif
}

__device__ __forceinline__ void mma_bf16_ss(uint32_t d, uint64_t a, uint64_t b,
                                            uint32_t idesc, uint32_t acc) {
#if HAS_TCGEN05
    uint32_t z = 0;
    asm volatile(
        "{\n\t.reg .pred p;\n\tsetp.ne.u32 p, %5, 0;\n\t"
        "tcgen05.mma.cta_group::1.kind::f16 [%0], %1, %2, %3, {%4,%4,%4,%4}, p;\n\t}"
        :: "r"(d), "l"(a), "l"(b), "r"(idesc), "r"(z), "r"(acc) : "memory");
#endif
}

// SW64 swizzle (atom = 8 rows x 64 B) + descriptor  (proven correct R7/R10/R13)
__device__ __forceinline__ uint32_t swz64(uint32_t off) { return off ^ ((off >> 3) & 0x30); }
static constexpr uint64_t DESC_BASE_SW64 =
    (uint64_t(4) << 61) | (uint64_t(1) << 46) | (uint64_t(32) << 32) | (uint64_t(1) << 16);
__device__ __forceinline__ uint64_t mk_desc64(uint32_t addr) {
    return DESC_BASE_SW64 | ((uint64_t)(addr >> 4) & 0x3FFF);
}

// idesc: dtype=F32, atype=btype=BF16, M=128 (per MMA), N=256
#define MMA_IDESC ((1u << 4) | (1u << 7) | (1u << 10) | ((256u / 8) << 17) | ((128u / 16) << 24))

// ---------------- bf16 split / pack --------------------------------------------
__device__ __forceinline__ void split_pack(float f0, float f1,
                                           uint32_t& H, uint32_t& L) {
    __nv_bfloat16 h0 = __float2bfloat16(f0);
    __nv_bfloat16 h1 = __float2bfloat16(f1);
    __nv_bfloat16 l0 = __float2bfloat16(f0 - __bfloat162float(h0));
    __nv_bfloat16 l1 = __float2bfloat16(f1 - __bfloat162float(h1));
    unsigned short uh0 = *(unsigned short*)&h0, uh1 = *(unsigned short*)&h1;
    unsigned short ul0 = *(unsigned short*)&l0, ul1 = *(unsigned short*)&l1;
    H = ((uint32_t)uh1 << 16) | uh0;
    L = ((uint32_t)ul1 << 16) | ul0;
}
__device__ __forceinline__ void split_bf16(float x, __nv_bfloat16& hi, __nv_bfloat16& lo) {
    hi = __float2bfloat16(x);
    lo = __float2bfloat16(x - __bfloat162float(hi));
}
__device__ __forceinline__ void unpack2(uint32_t w, float& a, float& b) {
    __nv_bfloat162 t = *(__nv_bfloat162*)&w;
    a = __bfloat162float(t.x);
    b = __bfloat162float(t.y);
}

// ---------------- cg1 tensor GEMM, 256x256 CTA tile, warp-specialized ---------
#define BMC 256
#define BN  256
#define KS  32
#define NIT (DIM / KS)                 // 64
#define NSTAGE 3
#define OP_BYTES (256 * 64)            // 16 KB
#define STAGE_BYTES (4 * OP_BYTES)     // 64 KB
#define SMEM_DATA 1024
#define SMEM_TOT (SMEM_DATA + NSTAGE * STAGE_BYTES)
#define MB_FULL(s) (sb + 16 + (s) * 8)
#define MB_DONE(s) (sb + 48 + (s) * 8)
#define NLOAD 128

__device__ __forceinline__ void load_op256_w(uint32_t dst, const __nv_bfloat16* g,
                                             int k0, int ltid) {
#pragma unroll
    for (int i = 0; i < 8; i++) {
        int idx = i * NLOAD + ltid;
        int r = idx >> 2;
        int c = idx & 3;
        CP_ASYNC16(dst + swz64((uint32_t)(r * 64 + c * 16)),
                   g + (size_t)r * DIM + k0 + c * 8);
    }
}

__device__ __forceinline__ void load_stage_w(
    uint32_t sbase, int s, int k0,
    const __nv_bfloat16* Ah, const __nv_bfloat16* Al,
    const __nv_bfloat16* Bh, const __nv_bfloat16* Bl, int ltid) {
    uint32_t st = sbase + SMEM_DATA + s * STAGE_BYTES;
    load_op256_w(st, Ah, k0, ltid);
    load_op256_w(st + OP_BYTES, Al, k0, ltid);
    load_op256_w(st + 2 * OP_BYTES, Bh, k0, ltid);
    load_op256_w(st + 3 * OP_BYTES, Bl, k0, ltid);
}

// EPI 0 (GEMM1): T = tanh(sc[m]*acc + b1) -> Ohi/Olo.
// EPI 1 (GEMM2): delta = acc + b2; fused update in coalesced phase:
//   x = sc*keep*h_u + delta + sum(c_k*dir_k); h <- x (hi/lo); partial stats.
template <int EPI>
__global__ void __launch_bounds__(256, 1)
gemm_tc(const __nv_bfloat16* __restrict__ Ahi, const __nv_bfloat16* __restrict__ Alo,
        const __nv_bfloat16* __restrict__ Bhi, const __nv_bfloat16* __restrict__ Blo,
        const float* __restrict__ bias,
        __nv_bfloat16* __restrict__ Ohi, __nv_bfloat16* __restrict__ Olo) {
    extern __shared__ char smem[];
    uint32_t sb = smem_u32(smem);
    const int tid = threadIdx.x;
    const int wid = tid >> 5;
    const int lid = tid & 31;
    const int bm = blockIdx.y * BMC;
    const int bn = blockIdx.x * BN;

    if (wid == 0) TCGEN05_ALLOC(sb, 512);
    if (tid == 0) {
#pragma unroll
        for (int s = 0; s < NSTAGE; s++) {
            MBARRIER_INIT(MB_FULL(s), NLOAD);
            MBARRIER_INIT(MB_DONE(s), 1);
        }
    }
    __syncthreads();
    uint32_t tmem;
    asm volatile("ld.shared.b32 %0, [%1];" : "=r"(tmem) : "r"(sb));
    if (wid == 0) TCGEN05_RELINQ();
    __syncthreads();

    const __nv_bfloat16* Ah = Ahi + (size_t)bm * DIM;
    const __nv_bfloat16* Al = Alo + (size_t)bm * DIM;
    const __nv_bfloat16* Bh = Bhi + (size_t)bn * DIM;
    const __nv_bfloat16* Bl = Blo + (size_t)bn * DIM;

    if (tid >= 128) {
        const int ltid = tid - 128;
#pragma unroll
        for (int s = 0; s < NSTAGE; s++) {
            load_stage_w(sb, s, s * KS, Ah, Al, Bh, Bl, ltid);
            CP_ASYNC_MBAR_ARRIVE(MB_FULL(s));
        }
        for (int it = 0; it + NSTAGE < NIT; it++) {
            const int s = it % NSTAGE;
            const uint32_t ph = (uint32_t)(it / NSTAGE) & 1u;
            mbar_wait(MB_DONE(s), ph);
            load_stage_w(sb, s, (it + NSTAGE) * KS, Ah, Al, Bh, Bl, ltid);
            CP_ASYNC_MBAR_ARRIVE(MB_FULL(s));
        }
        // loaders are phase-exact on done[]; only they take the final wait (R9 lesson)
        mbar_wait(MB_DONE((NIT - 1) % NSTAGE), (uint32_t)((NIT - 1) / NSTAGE) & 1u);
    } else if (tid == 0) {
        for (int it = 0; it < NIT; it++) {
            const int s = it % NSTAGE;
            const uint32_t ph = (uint32_t)(it / NSTAGE) & 1u;
            mbar_wait(MB_FULL(s), ph);
            FENCE_PROXY_ASYNC();
            uint32_t st = sb + SMEM_DATA + s * STAGE_BYTES;
            uint64_t dAh = mk_desc64(st);
            uint64_t dAl = mk_desc64(st + OP_BYTES);
            uint64_t dBh = mk_desc64(st + 2 * OP_BYTES);
            uint64_t dBl = mk_desc64(st + 3 * OP_BYTES);
#pragma unroll
            for (int j = 0; j < 2; j++) {
#pragma unroll
                for (int m = 0; m < 2; m++) {
                    uint64_t aoff = (uint64_t)(m * 512 + j * 2);
                    uint32_t d = tmem + m * 256;
                    mma_bf16_ss(d, dAh + aoff, dBh + j * 2, MMA_IDESC, !(it == 0 && j == 0));
                    mma_bf16_ss(d, dAh + aoff, dBl + j * 2, MMA_IDESC, 1u);
                    mma_bf16_ss(d, dAl + aoff, dBh + j * 2, MMA_IDESC, 1u);
                }
            }
            TCGEN05_COMMIT(MB_DONE(s));
        }
    }

    __syncthreads();
    TCGEN05_FENCE_AFTER();

    // ---- transposed epilogue: TMEM -> SMEM -> coalesced global ----
    const uint32_t SH_H = sb + SMEM_DATA;
    const uint32_t SH_L = SH_H + 128 * 512;
    for (int a = 0; a < 2; a++) {
        const int mlane = (wid & 3) * 32 + lid;
        const int colh = (wid >> 2) * 128;
        const uint32_t tb = tmem + a * 256 + colh;
        const float scrow = (EPI == 0) ? g_coef4[bm + a * 128 + mlane].w : 0.f;
        // phase 1: TMEM -> compute -> swizzled SMEM
#pragma unroll
        for (int cb = 0; cb < 128; cb += 32) {
            uint32_t r[32];
            tcgen05_ld32x32(r, tb + cb);
            TCGEN05_WAIT_LD();
#pragma unroll
            for (int c = 0; c < 32; c += 8) {
                uint32_t H[4], L[4];
#pragma unroll
                for (int k = 0; k < 4; k++) {
                    int n = bn + colh + cb + c + k * 2;
                    float f0, f1;
                    if (EPI == 0) {
                        f0 = tanhf(fmaf(__uint_as_float(r[c + k * 2]), scrow, bias[n]));
                        f1 = tanhf(fmaf(__uint_as_float(r[c + k * 2 + 1]), scrow, bias[n + 1]));
                    } else {
                        f0 = __uint_as_float(r[c + k * 2]) + bias[n];
                        f1 = __uint_as_float(r[c + k * 2 + 1]) + bias[n + 1];
                    }
                    split_pack(f0, f1, H[k], L[k]);
                }
                uint32_t colbyte = (uint32_t)(colh + cb + c) * 2;
                uint32_t off = (uint32_t)mlane * 512 + (colbyte ^ (((uint32_t)mlane & 7) << 4));
                STS128(SH_H + off, H[0], H[1], H[2], H[3]);
                STS128(SH_L + off, L[0], L[1], L[2], L[3]);
            }
        }
        __syncthreads();
        // phase 2: coalesced readback
#pragma unroll
        for (int g = 0; g < 4; g++) {
            int row = wid * 16 + g * 4 + (lid >> 3);
            int grow = bm + a * 128 + row;
            size_t gbase = ((size_t)grow * DIM + bn) * 2;
            if (EPI == 0) {
#pragma unroll
                for (int ln = 0; ln < 4; ln++) {
                    uint32_t cbyte = (uint32_t)(ln * 128 + (lid & 7) * 16);
                    uint32_t src = (uint32_t)row * 512 + (cbyte ^ (((uint32_t)row & 7) << 4));
                    uint32_t h0, h1, h2, h3, l0, l1, l2, l3;
                    LDS128(h0, h1, h2, h3, SH_H + src);
                    LDS128(l0, l1, l2, l3, SH_L + src);
                    *(uint4*)((char*)Ohi + gbase + cbyte) = make_uint4(h0, h1, h2, h3);
                    *(uint4*)((char*)Olo + gbase + cbyte) = make_uint4(l0, l1, l2, l3);
                }
            } else {
                // fused update (math proven in R12, coalesced pattern from R13)
                float4 cf = g_coef4[grow];
                float ksc = cf.w * (1.f - (cf.x + cf.y + cf.z));
                float sx = 0.f, se = 0.f, sv = 0.f, sn = 0.f;
#pragma unroll
                for (int ln = 0; ln < 4; ln++) {
                    uint32_t cbyte = (uint32_t)(ln * 128 + (lid & 7) * 16);
                    uint32_t src = (uint32_t)row * 512 + (cbyte ^ (((uint32_t)row & 7) << 4));
                    uint32_t dH[4], dL[4];
                    LDS128(dH[0], dH[1], dH[2], dH[3], SH_H + src);
                    LDS128(dL[0], dL[1], dL[2], dL[3], SH_L + src);
                    uint4 vh = *(uint4*)((char*)Ohi + gbase + cbyte);
                    uint4 vl = *(uint4*)((char*)Olo + gbase + cbyte);
                    uint32_t hh[4] = {vh.x, vh.y, vh.z, vh.w};
                    uint32_t hl[4] = {vl.x, vl.y, vl.z, vl.w};
                    int n0 = bn + (int)(cbyte >> 1);
                    float ev[8], cv[8], nv[8];
                    *(float4*)&ev[0] = *(const float4*)&g_dirs[n0];
                    *(float4*)&ev[4] = *(const float4*)&g_dirs[n0 + 4];
                    *(float4*)&cv[0] = *(const float4*)&g_dirs[DIM + n0];
                    *(float4*)&cv[4] = *(const float4*)&g_dirs[DIM + n0 + 4];
                    *(float4*)&nv[0] = *(const float4*)&g_dirs[2 * DIM + n0];
                    *(float4*)&nv[4] = *(const float4*)&g_dirs[2 * DIM + n0 + 4];
                    uint32_t oH[4], oL[4];
#pragma unroll
                    for (int k = 0; k < 4; k++) {
                        float d0, d1, dl0, dl1, u0, u1, ul0, ul1;
                        unpack2(dH[k], d0, d1);
                        unpack2(dL[k], dl0, dl1);
                        unpack2(hh[k], u0, u1);
                        unpack2(hl[k], ul0, ul1);
                        float del0 = d0 + dl0, del1 = d1 + dl1;
                        float hu0 = u0 + ul0, hu1 = u1 + ul1;
                        float e0 = ev[2 * k], e1 = ev[2 * k + 1];
                        float c0 = cv[2 * k], c1 = cv[2 * k + 1];
                        float q0 = nv[2 * k], q1 = nv[2 * k + 1];
                        float x0 = fmaf(hu0, ksc, del0) + cf.x * e0 + cf.y * c0 + cf.z * q0;
                        float x1 = fmaf(hu1, ksc, del1) + cf.x * e1 + cf.y * c1 + cf.z * q1;
                        sx = fmaf(x0, x0, sx); sx = fmaf(x1, x1, sx);
                        se = fmaf(x0, e0, se); se = fmaf(x1, e1, se);
                        sv = fmaf(x0, c0, sv); sv = fmaf(x1, c1, sv);
                        sn = fmaf(x0, q0, sn); sn = fmaf(x1, q1, sn);
                        split_pack(x0, x1, oH[k], oL[k]);
                    }
                    *(uint4*)((char*)Ohi + gbase + cbyte) = make_uint4(oH[0], oH[1], oH[2], oH[3]);
                    *(uint4*)((char*)Olo + gbase + cbyte) = make_uint4(oL[0], oL[1], oL[2], oL[3]);
                }
                // reduce over the 8 lanes covering this row
#pragma unroll
                for (int o = 1; o < 8; o <<= 1) {
                    sx += __shfl_xor_sync(0xffffffffu, sx, o);
                    se += __shfl_xor_sync(0xffffffffu, se, o);
                    sv += __shfl_xor_sync(0xffffffffu, sv, o);
                    sn += __shfl_xor_sync(0xffffffffu, sn, o);
                }
                if ((lid & 7) == 0)
                    g_part[(size_t)grow * 8 + blockIdx.x] = make_float4(sx, se, sv, sn);
            }
        }
        __syncthreads();
    }

    if (tid == 0) {
#pragma unroll
        for (int s = 0; s < NSTAGE; s++) { MBARRIER_INVAL(MB_FULL(s)); MBARRIER_INVAL(MB_DONE(s)); }
    }
    __syncthreads();
    if (wid == 0) TCGEN05_DEALLOC(tmem, 512);
}

// ---------------- row coefs ----------------------------------------------------
__device__ __forceinline__ void store_coefs(int row, float nh2,
                                            float de, float dc, float dn, float sc) {
    float nh = sqrtf(nh2);
    float inv = 1.f / fmaxf(nh, 1e-12f);
    float dots[3] = {de, dc, dn};
    float out[3];
#pragma unroll
    for (int k = 0; k < 3; k++) {
        float a = dots[k] * inv;
        float r = sqrtf(fmaxf(nh2 - 2.f * dots[k] + 1.f, 0.f));
        out[k] = kS[k] * (DIVC - a) / fmaxf(r, 1e-12f);
    }
    g_coef4[row] = make_float4(out[0], out[1], out[2], sc);
}

__global__ void finalize_kernel() {
    int row = blockIdx.x * blockDim.x + threadIdx.x;
    if (row >= BATCH) return;
    float4 s = make_float4(0.f, 0.f, 0.f, 0.f);
#pragma unroll
    for (int j = 0; j < 8; j++) {
        float4 p = g_part[(size_t)row * 8 + j];
        s.x += p.x; s.y += p.y; s.z += p.z; s.w += p.w;
    }
    float norm = sqrtf(s.x);
    float sc = (norm > CAPV) ? (CAPV / (norm + 1e-8f)) : 1.f;
    store_coefs(row, sc * sc * s.x, sc * s.y, sc * s.z, sc * s.w, sc);
}

__global__ void final_out_kernel(const __nv_bfloat16* __restrict__ hhi,
                                 const __nv_bfloat16* __restrict__ hlo,
                                 float* __restrict__ hout) {
    int row = blockIdx.x;
    int t = threadIdx.x;
    float sc = g_coef4[row].w;
#pragma unroll
    for (int j = 0; j < DIM / 256; j++) {
        int i = t + j * 256;
        size_t idx = (size_t)row * DIM + i;
        hout[idx] = sc * (__bfloat162float(hhi[idx]) + __bfloat162float(hlo[idx]));
    }
}

// ---------------- block reduction of 4 sums ----------------------------------
__device__ __forceinline__ float4 block_reduce4(float4 v) {
    __shared__ float4 sh[8];
    int lane = threadIdx.x & 31;
    int w = threadIdx.x >> 5;
#pragma unroll
    for (int o = 16; o; o >>= 1) {
        v.x += __shfl_xor_sync(0xffffffffu, v.x, o);
        v.y += __shfl_xor_sync(0xffffffffu, v.y, o);
        v.z += __shfl_xor_sync(0xffffffffu, v.z, o);
        v.w += __shfl_xor_sync(0xffffffffu, v.w, o);
    }
    if (lane == 0) sh[w] = v;
    __syncthreads();
    if (w == 0) {
        float4 t = (lane < 8) ? sh[lane] : make_float4(0.f, 0.f, 0.f, 0.f);
#pragma unroll
        for (int o = 4; o; o >>= 1) {
            t.x += __shfl_xor_sync(0xffffffffu, t.x, o);
            t.y += __shfl_xor_sync(0xffffffffu, t.y, o);
            t.z += __shfl_xor_sync(0xffffffffu, t.z, o);
            t.w += __shfl_xor_sync(0xffffffffu, t.w, o);
        }
        if (lane == 0) sh[0] = t;
    }
    __syncthreads();
    return sh[0];
}

// ---------------- small prep kernels ------------------------------------------
__global__ void prep_dirs_kernel(const float* __restrict__ e,
                                 const float* __restrict__ c,
                                 const float* __restrict__ n) {
    const float* src = (blockIdx.x == 0) ? e : (blockIdx.x == 1 ? c : n);
    float4 s = make_float4(0.f, 0.f, 0.f, 0.f);
    for (int i = threadIdx.x; i < DIM; i += 256) {
        float v = src[i];
        s.x += v * v;
    }
    s = block_reduce4(s);
    float inv = 1.f / fmaxf(sqrtf(s.x), 1e-12f);
    for (int i = threadIdx.x; i < DIM; i += 256)
        g_dirs[blockIdx.x * DIM + i] = src[i] * inv;
}

__global__ void init_kernel(const float* __restrict__ h0,
                            __nv_bfloat16* __restrict__ hhi,
                            __nv_bfloat16* __restrict__ hlo) {
    int row = blockIdx.x;
    int t = threadIdx.x;
    const float* hr = h0 + (size_t)row * DIM;
    float4 s = make_float4(0.f, 0.f, 0.f, 0.f);
#pragma unroll
    for (int j = 0; j < DIM / 256; j++) {
        int i = t + j * 256;
        float v = hr[i];
        s.x += v * v;
        s.y += v * g_dirs[i];
        s.z += v * g_dirs[DIM + i];
        s.w += v * g_dirs[2 * DIM + i];
        __nv_bfloat16 hi, lo;
        split_bf16(v, hi, lo);
        hhi[(size_t)row * DIM + i] = hi;
        hlo[(size_t)row * DIM + i] = lo;
    }
    s = block_reduce4(s);
    if (t == 0) store_coefs(row, s.x, s.y, s.z, s.w, 1.f);
}

__global__ void conv_split_kernel(const float* __restrict__ src,
                                  __nv_bfloat16* __restrict__ hi,
                                  __nv_bfloat16* __restrict__ lo, size_t n) {
    size_t i = (size_t)blockIdx.x * blockDim.x + threadIdx.x;
    if (i < n) {
        __nv_bfloat16 h, l;
        split_bf16(src[i], h, l);
        hi[i] = h;
        lo[i] = l;
    }
}

// ---------------- launch --------------------------------------------------------
extern "C" void kernel_launch(void* const* d_in, const int* in_sizes, int n_in,
                              void* d_out, int out_size) {
    const float* h0 = (const float*)d_in[0];
    const float* ae = (const float*)d_in[1];
    const float* ac = (const float*)d_in[2];
    const float* an = (const float*)d_in[3];
    const float* W1 = (const float*)d_in[4];
    const float* b1 = (const float*)d_in[5];
    const float* W2 = (const float*)d_in[6];
    const float* b2 = (const float*)d_in[7];
    float* h = (float*)d_out;

    __nv_bfloat16 *hhi, *hlo, *Thi, *Tlo, *W1h, *W1l, *W2h, *W2l;
    cudaGetSymbolAddress((void**)&hhi, g_hhi);
    cudaGetSymbolAddress((void**)&hlo, g_hlo);
    cudaGetSymbolAddress((void**)&Thi, g_Thi);
    cudaGetSymbolAddress((void**)&Tlo, g_Tlo);
    cudaGetSymbolAddress((void**)&W1h, g_W1hi);
    cudaGetSymbolAddress((void**)&W1l, g_W1lo);
    cudaGetSymbolAddress((void**)&W2h, g_W2hi);
    cudaGetSymbolAddress((void**)&W2l, g_W2lo);

    cudaFuncSetAttribute(gemm_tc<0>, cudaFuncAttributeMaxDynamicSharedMemorySize, SMEM_TOT);
    cudaFuncSetAttribute(gemm_tc<1>, cudaFuncAttributeMaxDynamicSharedMemorySize, SMEM_TOT);

    size_t nw = (size_t)DIM * DIM;
    conv_split_kernel<<<(unsigned)((nw + 1023) / 1024), 1024>>>(W1, W1h, W1l, nw);
    conv_split_kernel<<<(unsigned)((nw + 1023) / 1024), 1024>>>(W2, W2h, W2l, nw);
    prep_dirs_kernel<<<3, 256>>>(ae, ac, an);
    init_kernel<<<BATCH, 256>>>(h0, hhi, hlo);

    dim3 ggrid(DIM / BN, BATCH / BMC);   // (8, 64) = 512 CTAs
    for (int l = 0; l < NLAYERS; l++) {
        gemm_tc<0><<<ggrid, 256, SMEM_TOT>>>(hhi, hlo, W1h, W1l, b1, Thi, Tlo);
        gemm_tc<1><<<ggrid, 256, SMEM_TOT>>>(Thi, Tlo, W2h, W2l, b2, hhi, hlo);
        finalize_kernel<<<BATCH / 256, 256>>>();
    }
    final_out_kernel<<<BATCH, 256>>>(hhi, hlo, h);
}

// round 15
// speedup vs baseline: 1.0665x; 1.0665x over previous
#include <cuda_runtime.h>
#include <cuda_bf16.h>
#include <math.h>
#include <stdint.h>

#define DIM    2048
#define BATCH  16384
#define NLAYERS 4

static __device__ __constant__ float kS[3] = {0.1f, 0.1f, 0.05f};
#define DIVC 0.38f
#define CAPV 10.0f

#if defined(__CUDA_ARCH_FEAT_SM103_ALL) || defined(__CUDA_ARCH_FEAT_SM100_ALL) || defined(__CUDA_ARCH_FEAT_SM101_ALL)
#define HAS_TCGEN05 1
#else
#define HAS_TCGEN05 0
#endif

// ---------------- scratch (static device globals; no allocation) -------------
__device__ __nv_bfloat16 g_hhi[(size_t)BATCH * DIM];
__device__ __nv_bfloat16 g_hlo[(size_t)BATCH * DIM];
__device__ __nv_bfloat16 g_Thi[(size_t)BATCH * DIM];
__device__ __nv_bfloat16 g_Tlo[(size_t)BATCH * DIM];
__device__ __nv_bfloat16 g_Dhi[(size_t)BATCH * DIM];
__device__ __nv_bfloat16 g_Dlo[(size_t)BATCH * DIM];
__device__ __nv_bfloat16 g_W1hi[(size_t)DIM * DIM];
__device__ __nv_bfloat16 g_W1lo[(size_t)DIM * DIM];
__device__ __nv_bfloat16 g_W2hi[(size_t)DIM * DIM];
__device__ __nv_bfloat16 g_W2lo[(size_t)DIM * DIM];
__device__ float g_dirs[3 * DIM];
__device__ float g_coef[(size_t)BATCH * 4];

// ---------------- PTX helpers -------------------------------------------------
__device__ __forceinline__ uint32_t smem_u32(const void* p) {
    uint32_t a;
    asm("{ .reg .u64 t; cvta.to.shared.u64 t, %1; cvt.u32.u64 %0, t; }" : "=r"(a) : "l"(p));
    return a;
}

#if HAS_TCGEN05
#define TCGEN05_ALLOC(sm, n) \
    asm volatile("tcgen05.alloc.cta_group::1.sync.aligned.shared::cta.b32 [%0], %1;" :: "r"(sm), "r"(n) : "memory")
#define TCGEN05_RELINQ() \
    asm volatile("tcgen05.relinquish_alloc_permit.cta_group::1.sync.aligned;")
#define TCGEN05_DEALLOC(t, n) \
    asm volatile("tcgen05.dealloc.cta_group::1.sync.aligned.b32 %0, %1;" :: "r"(t), "r"(n))
#define TCGEN05_COMMIT(mb) \
    asm volatile("tcgen05.commit.cta_group::1.mbarrier::arrive::one.shared::cluster.b64 [%0];" :: "r"(mb) : "memory")
#define TCGEN05_FENCE_AFTER() asm volatile("tcgen05.fence::after_thread_sync;" ::: "memory")
#define TCGEN05_WAIT_LD() asm volatile("tcgen05.wait::ld.sync.aligned;" ::: "memory")
#else
#define TCGEN05_ALLOC(sm, n)   ((void)0)
#define TCGEN05_RELINQ()       ((void)0)
#define TCGEN05_DEALLOC(t, n)  ((void)0)
#define TCGEN05_COMMIT(mb)     ((void)0)
#define TCGEN05_FENCE_AFTER()  ((void)0)
#define TCGEN05_WAIT_LD()      ((void)0)
#endif

#define MBARRIER_INIT(mb, c) \
    asm volatile("mbarrier.init.shared.b64 [%0], %1;" :: "r"(mb), "r"(c) : "memory")
#define MBARRIER_INVAL(mb) \
    asm volatile("mbarrier.inval.shared.b64 [%0];" :: "r"(mb) : "memory")
#define FENCE_PROXY_ASYNC() asm volatile("fence.proxy.async.shared::cta;" ::: "memory")
#define CP_ASYNC16(dst, src) \
    asm volatile("cp.async.cg.shared.global [%0], [%1], 16;" :: "r"(dst), "l"(src) : "memory")
#define CP_ASYNC_MBAR_ARRIVE(mb) \
    asm volatile("cp.async.mbarrier.arrive.noinc.shared::cta.b64 [%0];" :: "r"(mb) : "memory")
#define STS128(addr, a, b, c, d) \
    asm volatile("st.shared.v4.b32 [%0], {%1,%2,%3,%4};" :: "r"(addr), "r"(a), "r"(b), "r"(c), "r"(d) : "memory")
#define LDS128(a, b, c, d, addr) \
    asm volatile("ld.shared.v4.b32 {%0,%1,%2,%3}, [%4];" : "=r"(a), "=r"(b), "=r"(c), "=r"(d) : "r"(addr))

__device__ __forceinline__ void mbar_wait(uint32_t mb, uint32_t parity) {
    uint32_t done;
    asm volatile(
        "{\n\t.reg .pred p;\n\t"
        "mbarrier.try_wait.parity.acquire.cta.shared::cta.b64 p, [%1], %2;\n\t"
        "selp.b32 %0, 1, 0, p;\n\t}"
        : "=r"(done) : "r"(mb), "r"(parity) : "memory");
    if (!done) {
        asm volatile(
            "{\n\t.reg .pred P1;\n\t"
            "W_%=:\n\t"
            "mbarrier.try_wait.parity.acquire.cta.shared::cta.b64 P1, [%0], %1, 0x989680;\n\t"
            "@P1 bra.uni D_%=;\n\t"
            "bra.uni W_%=;\n\t"
            "D_%=:\n\t}"
            :: "r"(mb), "r"(parity) : "memory");
    }
}

__device__ __forceinline__ void tcgen05_ld32x32(uint32_t* r, uint32_t addr) {
#if HAS_TCGEN05
    asm volatile(
        "tcgen05.ld.sync.aligned.32x32b.x32.b32 "
        "{%0,%1,%2,%3,%4,%5,%6,%7,%8,%9,%10,%11,%12,%13,%14,%15,"
        "%16,%17,%18,%19,%20,%21,%22,%23,%24,%25,%26,%27,%28,%29,%30,%31}, [%32];"
        : "=r"(r[0]), "=r"(r[1]), "=r"(r[2]), "=r"(r[3]), "=r"(r[4]), "=r"(r[5]), "=r"(r[6]), "=r"(r[7]),
          "=r"(r[8]), "=r"(r[9]), "=r"(r[10]), "=r"(r[11]), "=r"(r[12]), "=r"(r[13]), "=r"(r[14]), "=r"(r[15]),
          "=r"(r[16]), "=r"(r[17]), "=r"(r[18]), "=r"(r[19]), "=r"(r[20]), "=r"(r[21]), "=r"(r[22]), "=r"(r[23]),
          "=r"(r[24]), "=r"(r[25]), "=r"(r[26]), "=r"(r[27]), "=r"(r[28]), "=r"(r[29]), "=r"(r[30]), "=r"(r[31])
        : "r"(addr));
#else
    for (int i = 0; i < 32; i++) r[i] = 0;
#endif
}

__device__ __forceinline__ void mma_bf16_ss(uint32_t d, uint64_t a, uint64_t b,
                                            uint32_t idesc, uint32_t acc) {
#if HAS_TCGEN05
    uint32_t z = 0;
    asm volatile(
        "{\n\t.reg .pred p;\n\tsetp.ne.u32 p, %5, 0;\n\t"
        "tcgen05.mma.cta_group::1.kind::f16 [%0], %1, %2, %3, {%4,%4,%4,%4}, p;\n\t}"
        :: "r"(d), "l"(a), "l"(b), "r"(idesc), "r"(z), "r"(acc) : "memory");
#endif
}

// SW64 swizzle (atom = 8 rows x 64 B) + descriptor  (proven correct R7/R10/R13)
__device__ __forceinline__ uint32_t swz64(uint32_t off) { return off ^ ((off >> 3) & 0x30); }
static constexpr uint64_t DESC_BASE_SW64 =
    (uint64_t(4) << 61) | (uint64_t(1) << 46) | (uint64_t(32) << 32) | (uint64_t(1) << 16);
__device__ __forceinline__ uint64_t mk_desc64(uint32_t addr) {
    return DESC_BASE_SW64 | ((uint64_t)(addr >> 4) & 0x3FFF);
}

// idesc: dtype=F32, atype=btype=BF16, M=128 (per MMA), N=256
#define MMA_IDESC ((1u << 4) | (1u << 7) | (1u << 10) | ((256u / 8) << 17) | ((128u / 16) << 24))

// ---------------- math helpers --------------------------------------------------
// fast tanh: (1-e)/(1+e), e = exp(-2|x|)  — abs err ~2e-7, far below bf16-split noise
__device__ __forceinline__ float fast_tanh(float x) {
    float t = fabsf(x);
    float e = __expf(-2.f * t);
    float r = __fdividef(1.f - e, 1.f + e);
    return copysignf(r, x);
}
__device__ __forceinline__ void split_pack(float f0, float f1,
                                           uint32_t& H, uint32_t& L) {
    __nv_bfloat16 h0 = __float2bfloat16(f0);
    __nv_bfloat16 h1 = __float2bfloat16(f1);
    __nv_bfloat16 l0 = __float2bfloat16(f0 - __bfloat162float(h0));
    __nv_bfloat16 l1 = __float2bfloat16(f1 - __bfloat162float(h1));
    unsigned short uh0 = *(unsigned short*)&h0, uh1 = *(unsigned short*)&h1;
    unsigned short ul0 = *(unsigned short*)&l0, ul1 = *(unsigned short*)&l1;
    H = ((uint32_t)uh1 << 16) | uh0;
    L = ((uint32_t)ul1 << 16) | ul0;
}
__device__ __forceinline__ void split_bf16(float x, __nv_bfloat16& hi, __nv_bfloat16& lo) {
    hi = __float2bfloat16(x);
    lo = __float2bfloat16(x - __bfloat162float(hi));
}
__device__ __forceinline__ void unpack2(uint32_t w, float& a, float& b) {
    __nv_bfloat162 t = *(__nv_bfloat162*)&w;
    a = __bfloat162float(t.x);
    b = __bfloat162float(t.y);
}

// ---------------- cg1 tensor GEMM, 256x256 CTA tile, warp-specialized ---------
// R13 structure (best): cp.async producer warps, single MMA issuer,
// SMEM-transposed coalesced epilogue.
#define BMC 256
#define BN  256
#define KS  32
#define NIT (DIM / KS)                 // 64
#define NSTAGE 3
#define OP_BYTES (256 * 64)            // 16 KB
#define STAGE_BYTES (4 * OP_BYTES)     // 64 KB
#define SMEM_DATA 1024
#define SMEM_TOT (SMEM_DATA + NSTAGE * STAGE_BYTES)
#define MB_FULL(s) (sb + 16 + (s) * 8)
#define MB_DONE(s) (sb + 48 + (s) * 8)
#define NLOAD 128

__device__ __forceinline__ void load_op256_w(uint32_t dst, const __nv_bfloat16* g,
                                             int k0, int ltid) {
#pragma unroll
    for (int i = 0; i < 8; i++) {
        int idx = i * NLOAD + ltid;
        int r = idx >> 2;
        int c = idx & 3;
        CP_ASYNC16(dst + swz64((uint32_t)(r * 64 + c * 16)),
                   g + (size_t)r * DIM + k0 + c * 8);
    }
}

__device__ __forceinline__ void load_stage_w(
    uint32_t sbase, int s, int k0,
    const __nv_bfloat16* Ah, const __nv_bfloat16* Al,
    const __nv_bfloat16* Bh, const __nv_bfloat16* Bl, int ltid) {
    uint32_t st = sbase + SMEM_DATA + s * STAGE_BYTES;
    load_op256_w(st, Ah, k0, ltid);
    load_op256_w(st + OP_BYTES, Al, k0, ltid);
    load_op256_w(st + 2 * OP_BYTES, Bh, k0, ltid);
    load_op256_w(st + 3 * OP_BYTES, Bl, k0, ltid);
}

// EPI 0: tanh(acc + bias) -> Ohi/Olo.   EPI 1: acc + bias -> Ohi/Olo (delta).
template <int EPI>
__global__ void __launch_bounds__(256, 1)
gemm_tc(const __nv_bfloat16* __restrict__ Ahi, const __nv_bfloat16* __restrict__ Alo,
        const __nv_bfloat16* __restrict__ Bhi, const __nv_bfloat16* __restrict__ Blo,
        const float* __restrict__ bias,
        __nv_bfloat16* __restrict__ Ohi, __nv_bfloat16* __restrict__ Olo) {
    extern __shared__ char smem[];
    uint32_t sb = smem_u32(smem);
    const int tid = threadIdx.x;
    const int wid = tid >> 5;
    const int lid = tid & 31;
    const int bm = blockIdx.y * BMC;
    const int bn = blockIdx.x * BN;

    if (wid == 0) TCGEN05_ALLOC(sb, 512);
    if (tid == 0) {
#pragma unroll
        for (int s = 0; s < NSTAGE; s++) {
            MBARRIER_INIT(MB_FULL(s), NLOAD);
            MBARRIER_INIT(MB_DONE(s), 1);
        }
    }
    __syncthreads();
    uint32_t tmem;
    asm volatile("ld.shared.b32 %0, [%1];" : "=r"(tmem) : "r"(sb));
    if (wid == 0) TCGEN05_RELINQ();
    __syncthreads();

    const __nv_bfloat16* Ah = Ahi + (size_t)bm * DIM;
    const __nv_bfloat16* Al = Alo + (size_t)bm * DIM;
    const __nv_bfloat16* Bh = Bhi + (size_t)bn * DIM;
    const __nv_bfloat16* Bl = Blo + (size_t)bn * DIM;

    if (tid >= 128) {
        const int ltid = tid - 128;
#pragma unroll
        for (int s = 0; s < NSTAGE; s++) {
            load_stage_w(sb, s, s * KS, Ah, Al, Bh, Bl, ltid);
            CP_ASYNC_MBAR_ARRIVE(MB_FULL(s));
        }
        for (int it = 0; it + NSTAGE < NIT; it++) {
            const int s = it % NSTAGE;
            const uint32_t ph = (uint32_t)(it / NSTAGE) & 1u;
            mbar_wait(MB_DONE(s), ph);
            load_stage_w(sb, s, (it + NSTAGE) * KS, Ah, Al, Bh, Bl, ltid);
            CP_ASYNC_MBAR_ARRIVE(MB_FULL(s));
        }
        // loaders are phase-exact on done[]; only they take the final wait (R9 lesson)
        mbar_wait(MB_DONE((NIT - 1) % NSTAGE), (uint32_t)((NIT - 1) / NSTAGE) & 1u);
    } else if (tid == 0) {
        for (int it = 0; it < NIT; it++) {
            const int s = it % NSTAGE;
            const uint32_t ph = (uint32_t)(it / NSTAGE) & 1u;
            mbar_wait(MB_FULL(s), ph);
            FENCE_PROXY_ASYNC();
            uint32_t st = sb + SMEM_DATA + s * STAGE_BYTES;
            uint64_t dAh = mk_desc64(st);
            uint64_t dAl = mk_desc64(st + OP_BYTES);
            uint64_t dBh = mk_desc64(st + 2 * OP_BYTES);
            uint64_t dBl = mk_desc64(st + 3 * OP_BYTES);
#pragma unroll
            for (int j = 0; j < 2; j++) {
#pragma unroll
                for (int m = 0; m < 2; m++) {
                    uint64_t aoff = (uint64_t)(m * 512 + j * 2);
                    uint32_t d = tmem + m * 256;
                    mma_bf16_ss(d, dAh + aoff, dBh + j * 2, MMA_IDESC, !(it == 0 && j == 0));
                    mma_bf16_ss(d, dAh + aoff, dBl + j * 2, MMA_IDESC, 1u);
                    mma_bf16_ss(d, dAl + aoff, dBh + j * 2, MMA_IDESC, 1u);
                }
            }
            TCGEN05_COMMIT(MB_DONE(s));
        }
    }

    __syncthreads();          // releases everyone after loaders saw final commit
    TCGEN05_FENCE_AFTER();

    // ---- transposed epilogue: TMEM -> SMEM tile -> coalesced STG ----
    const uint32_t SH_H = sb + SMEM_DATA;
    const uint32_t SH_L = SH_H + 128 * 512;
    for (int a = 0; a < 2; a++) {   // M-halves
        const int mlane = (wid & 3) * 32 + lid;      // TMEM lane = row in half
        const int colh = (wid >> 2) * 128;           // col range of this warp
        const uint32_t tb = tmem + a * 256 + colh;
        // phase 1: read TMEM cols, compute, store swizzled into SMEM
#pragma unroll
        for (int cb = 0; cb < 128; cb += 32) {
            uint32_t r[32];
            tcgen05_ld32x32(r, tb + cb);
            TCGEN05_WAIT_LD();
#pragma unroll
            for (int c = 0; c < 32; c += 8) {
                uint32_t H[4], L[4];
#pragma unroll
                for (int k = 0; k < 4; k++) {
                    int n = bn + colh + cb + c + k * 2;
                    float f0 = __uint_as_float(r[c + k * 2]) + bias[n];
                    float f1 = __uint_as_float(r[c + k * 2 + 1]) + bias[n + 1];
                    if (EPI == 0) { f0 = fast_tanh(f0); f1 = fast_tanh(f1); }
                    split_pack(f0, f1, H[k], L[k]);
                }
                uint32_t colbyte = (uint32_t)(colh + cb + c) * 2;
                uint32_t off = (uint32_t)mlane * 512 + (colbyte ^ (((uint32_t)mlane & 7) << 4));
                STS128(SH_H + off, H[0], H[1], H[2], H[3]);
                STS128(SH_L + off, L[0], L[1], L[2], L[3]);
            }
        }
        __syncthreads();
        // phase 2: coalesced 128B-line stores
#pragma unroll
        for (int g = 0; g < 4; g++) {
            int row = wid * 16 + g * 4 + (lid >> 3);
            size_t gbase = ((size_t)(bm + a * 128 + row) * DIM + bn) * 2;
#pragma unroll
            for (int ln = 0; ln < 4; ln++) {
                uint32_t cbyte = (uint32_t)(ln * 128 + (lid & 7) * 16);
                uint32_t src = (uint32_t)row * 512 + (cbyte ^ (((uint32_t)row & 7) << 4));
                uint32_t h0, h1, h2, h3, l0, l1, l2, l3;
                LDS128(h0, h1, h2, h3, SH_H + src);
                LDS128(l0, l1, l2, l3, SH_L + src);
                *(uint4*)((char*)Ohi + gbase + cbyte) = make_uint4(h0, h1, h2, h3);
                *(uint4*)((char*)Olo + gbase + cbyte) = make_uint4(l0, l1, l2, l3);
            }
        }
        __syncthreads();
    }

    if (tid == 0) {
#pragma unroll
        for (int s = 0; s < NSTAGE; s++) { MBARRIER_INVAL(MB_FULL(s)); MBARRIER_INVAL(MB_DONE(s)); }
    }
    __syncthreads();
    if (wid == 0) TCGEN05_DEALLOC(tmem, 512);
}

// ---------------- block reduction of 4 sums ----------------------------------
__device__ __forceinline__ float4 block_reduce4(float4 v) {
    __shared__ float4 sh[8];
    int lane = threadIdx.x & 31;
    int w = threadIdx.x >> 5;
#pragma unroll
    for (int o = 16; o; o >>= 1) {
        v.x += __shfl_xor_sync(0xffffffffu, v.x, o);
        v.y += __shfl_xor_sync(0xffffffffu, v.y, o);
        v.z += __shfl_xor_sync(0xffffffffu, v.z, o);
        v.w += __shfl_xor_sync(0xffffffffu, v.w, o);
    }
    if (lane == 0) sh[w] = v;
    __syncthreads();
    if (w == 0) {
        float4 t = (lane < 8) ? sh[lane] : make_float4(0.f, 0.f, 0.f, 0.f);
#pragma unroll
        for (int o = 4; o; o >>= 1) {
            t.x += __shfl_xor_sync(0xffffffffu, t.x, o);
            t.y += __shfl_xor_sync(0xffffffffu, t.y, o);
            t.z += __shfl_xor_sync(0xffffffffu, t.z, o);
            t.w += __shfl_xor_sync(0xffffffffu, t.w, o);
        }
        if (lane == 0) sh[0] = t;
    }
    __syncthreads();
    return sh[0];
}

__device__ __forceinline__ void write_coefs(int row, float nh2,
                                            float de, float dc, float dn) {
    float nh = sqrtf(nh2);
    float inv = 1.f / fmaxf(nh, 1e-12f);
    float dots[3] = {de, dc, dn};
#pragma unroll
    for (int k = 0; k < 3; k++) {
        float a = dots[k] * inv;
        float r = sqrtf(fmaxf(nh2 - 2.f * dots[k] + 1.f, 0.f));
        g_coef[(size_t)row * 4 + k] = kS[k] * (DIVC - a) / fmaxf(r, 1e-12f);
    }
}

// ---------------- small prep kernels ------------------------------------------
__global__ void prep_dirs_kernel(const float* __restrict__ e,
                                 const float* __restrict__ c,
                                 const float* __restrict__ n) {
    const float* src = (blockIdx.x == 0) ? e : (blockIdx.x == 1 ? c : n);
    float4 s = make_float4(0.f, 0.f, 0.f, 0.f);
    for (int i = threadIdx.x; i < DIM; i += 256) {
        float v = src[i];
        s.x += v * v;
    }
    s = block_reduce4(s);
    float inv = 1.f / fmaxf(sqrtf(s.x), 1e-12f);
    for (int i = threadIdx.x; i < DIM; i += 256)
        g_dirs[blockIdx.x * DIM + i] = src[i] * inv;
}

// fused: split h0 into hi/lo + compute layer-0 stats/coefs (vectorized, pair-wise)
__global__ void init_kernel(const float* __restrict__ h0,
                            __nv_bfloat16* __restrict__ hhi,
                            __nv_bfloat16* __restrict__ hlo) {
    int row = blockIdx.x;
    int t = threadIdx.x;
    const float2* hr = (const float2*)(h0 + (size_t)row * DIM);
    const float2* de = (const float2*)g_dirs;
    const float2* dc = (const float2*)(g_dirs + DIM);
    const float2* dn = (const float2*)(g_dirs + 2 * DIM);
    uint32_t* Hh = (uint32_t*)(g_hhi + (size_t)row * DIM);
    uint32_t* Hl = (uint32_t*)(g_hlo + (size_t)row * DIM);
    float4 s = make_float4(0.f, 0.f, 0.f, 0.f);
#pragma unroll
    for (int j = 0; j < 4; j++) {
        int p = t + j * 256;            // pair index (DIM/2 = 1024)
        float2 v = hr[p];
        float2 e = de[p], c = dc[p], n = dn[p];
        s.x = fmaf(v.x, v.x, s.x); s.x = fmaf(v.y, v.y, s.x);
        s.y = fmaf(v.x, e.x, s.y); s.y = fmaf(v.y, e.y, s.y);
        s.z = fmaf(v.x, c.x, s.z); s.z = fmaf(v.y, c.y, s.z);
        s.w = fmaf(v.x, n.x, s.w); s.w = fmaf(v.y, n.y, s.w);
        uint32_t H, L;
        split_pack(v.x, v.y, H, L);
        Hh[p] = H;
        Hl[p] = L;
    }
    s = block_reduce4(s);
    if (t == 0) write_coefs(row, s.x, s.y, s.z, s.w);
}

__global__ void conv_split_kernel(const float* __restrict__ src,
                                  __nv_bfloat16* __restrict__ hi,
                                  __nv_bfloat16* __restrict__ lo, size_t npair) {
    size_t p = (size_t)blockIdx.x * blockDim.x + threadIdx.x;
    if (p < npair) {
        float2 v = ((const float2*)src)[p];
        uint32_t H, L;
        split_pack(v.x, v.y, H, L);
        ((uint32_t*)hi)[p] = H;
        ((uint32_t*)lo)[p] = L;
    }
}

// ---------------- fused update + cap + stats + split (vectorized) --------------
__global__ void update_kernel(__nv_bfloat16* __restrict__ hhi,
                              __nv_bfloat16* __restrict__ hlo,
                              const __nv_bfloat16* __restrict__ Dhi,
                              const __nv_bfloat16* __restrict__ Dlo,
                              float* __restrict__ hout, int write_f32) {
    int row = blockIdx.x;
    int t = threadIdx.x;
    const uint32_t* Hh = (const uint32_t*)(hhi + (size_t)row * DIM);
    const uint32_t* Hl = (const uint32_t*)(hlo + (size_t)row * DIM);
    const uint32_t* Dh = (const uint32_t*)(Dhi + (size_t)row * DIM);
    const uint32_t* Dl = (const uint32_t*)(Dlo + (size_t)row * DIM);
    const float2* de = (const float2*)g_dirs;
    const float2* dc = (const float2*)(g_dirs + DIM);
    const float2* dn = (const float2*)(g_dirs + 2 * DIM);

    float ce = g_coef[(size_t)row * 4 + 0];
    float cc = g_coef[(size_t)row * 4 + 1];
    float cn = g_coef[(size_t)row * 4 + 2];
    float keep = 1.f - (ce + cc + cn);

    float2 x[4];
    float4 s = make_float4(0.f, 0.f, 0.f, 0.f);
#pragma unroll
    for (int j = 0; j < 4; j++) {
        int p = t + j * 256;
        float h0, h1, hl0, hl1, d0, d1, dl0, dl1;
        unpack2(Hh[p], h0, h1);
        unpack2(Hl[p], hl0, hl1);
        unpack2(Dh[p], d0, d1);
        unpack2(Dl[p], dl0, dl1);
        float2 e = de[p], c = dc[p], n = dn[p];
        float hv0 = h0 + hl0, hv1 = h1 + hl1;
        float dv0 = d0 + dl0, dv1 = d1 + dl1;
        float v0 = fmaf(hv0, keep, dv0) + ce * e.x + cc * c.x + cn * n.x;
        float v1 = fmaf(hv1, keep, dv1) + ce * e.y + cc * c.y + cn * n.y;
        x[j] = make_float2(v0, v1);
        s.x = fmaf(v0, v0, s.x); s.x = fmaf(v1, v1, s.x);
        s.y = fmaf(v0, e.x, s.y); s.y = fmaf(v1, e.y, s.y);
        s.z = fmaf(v0, c.x, s.z); s.z = fmaf(v1, c.y, s.z);
        s.w = fmaf(v0, n.x, s.w); s.w = fmaf(v1, n.y, s.w);
    }
    s = block_reduce4(s);
    float norm = sqrtf(s.x);
    float sc = (norm > CAPV) ? (CAPV / (norm + 1e-8f)) : 1.f;
    if (write_f32) {
        // last layer: only the fp32 output is needed
        float2* out = (float2*)(hout + (size_t)row * DIM);
#pragma unroll
        for (int j = 0; j < 4; j++) {
            int p = t + j * 256;
            out[p] = make_float2(x[j].x * sc, x[j].y * sc);
        }
    } else {
        uint32_t* Wh = (uint32_t*)(hhi + (size_t)row * DIM);
        uint32_t* Wl = (uint32_t*)(hlo + (size_t)row * DIM);
#pragma unroll
        for (int j = 0; j < 4; j++) {
            int p = t + j * 256;
            uint32_t H, L;
            split_pack(x[j].x * sc, x[j].y * sc, H, L);
            Wh[p] = H;
            Wl[p] = L;
        }
        if (t == 0)
            write_coefs(row, sc * sc * s.x, sc * s.y, sc * s.z, sc * s.w);
    }
}

// ---------------- launch --------------------------------------------------------
extern "C" void kernel_launch(void* const* d_in, const int* in_sizes, int n_in,
                              void* d_out, int out_size) {
    const float* h0 = (const float*)d_in[0];
    const float* ae = (const float*)d_in[1];
    const float* ac = (const float*)d_in[2];
    const float* an = (const float*)d_in[3];
    const float* W1 = (const float*)d_in[4];
    const float* b1 = (const float*)d_in[5];
    const float* W2 = (const float*)d_in[6];
    const float* b2 = (const float*)d_in[7];
    float* h = (float*)d_out;

    __nv_bfloat16 *hhi, *hlo, *Thi, *Tlo, *Dhi, *Dlo, *W1h, *W1l, *W2h, *W2l;
    cudaGetSymbolAddress((void**)&hhi, g_hhi);
    cudaGetSymbolAddress((void**)&hlo, g_hlo);
    cudaGetSymbolAddress((void**)&Thi, g_Thi);
    cudaGetSymbolAddress((void**)&Tlo, g_Tlo);
    cudaGetSymbolAddress((void**)&Dhi, g_Dhi);
    cudaGetSymbolAddress((void**)&Dlo, g_Dlo);
    cudaGetSymbolAddress((void**)&W1h, g_W1hi);
    cudaGetSymbolAddress((void**)&W1l, g_W1lo);
    cudaGetSymbolAddress((void**)&W2h, g_W2hi);
    cudaGetSymbolAddress((void**)&W2l, g_W2lo);

    cudaFuncSetAttribute(gemm_tc<0>, cudaFuncAttributeMaxDynamicSharedMemorySize, SMEM_TOT);
    cudaFuncSetAttribute(gemm_tc<1>, cudaFuncAttributeMaxDynamicSharedMemorySize, SMEM_TOT);

    size_t np = (size_t)DIM * DIM / 2;
    conv_split_kernel<<<(unsigned)((np + 511) / 512), 512>>>(W1, W1h, W1l, np);
    conv_split_kernel<<<(unsigned)((np + 511) / 512), 512>>>(W2, W2h, W2l, np);
    prep_dirs_kernel<<<3, 256>>>(ae, ac, an);
    init_kernel<<<BATCH, 256>>>(h0, hhi, hlo);

    dim3 ggrid(DIM / BN, BATCH / BMC);   // (8, 64) = 512 CTAs
    for (int l = 0; l < NLAYERS; l++) {
        gemm_tc<0><<<ggrid, 256, SMEM_TOT>>>(hhi, hlo, W1h, W1l, b1, Thi, Tlo);
        gemm_tc<1><<<ggrid, 256, SMEM_TOT>>>(Thi, Tlo, W2h, W2l, b2, Dhi, Dlo);
        update_kernel<<<BATCH, 256>>>(hhi, hlo, Dhi, Dlo, h, l == NLAYERS - 1);
    }
}

// round 17
// speedup vs baseline: 1.0756x; 1.0085x over previous
#include <cuda_runtime.h>
#include <cuda_bf16.h>
#include <math.h>
#include <stdint.h>

#define DIM    2048
#define BATCH  16384
#define NLAYERS 4

static __device__ __constant__ float kS[3] = {0.1f, 0.1f, 0.05f};
#define DIVC 0.38f
#define CAPV 10.0f

#if defined(__CUDA_ARCH_FEAT_SM103_ALL) || defined(__CUDA_ARCH_FEAT_SM100_ALL) || defined(__CUDA_ARCH_FEAT_SM101_ALL)
#define HAS_TCGEN05 1
#else
#define HAS_TCGEN05 0
#endif

// ---------------- scratch (static device globals; no allocation) -------------
__device__ __nv_bfloat16 g_hhi[(size_t)BATCH * DIM];
__device__ __nv_bfloat16 g_hlo[(size_t)BATCH * DIM];
__device__ __nv_bfloat16 g_Thi[(size_t)BATCH * DIM];
__device__ __nv_bfloat16 g_Tlo[(size_t)BATCH * DIM];
__device__ __nv_bfloat16 g_Dhi[(size_t)BATCH * DIM];
__device__ __nv_bfloat16 g_Dlo[(size_t)BATCH * DIM];
__device__ __nv_bfloat16 g_W1hi[(size_t)DIM * DIM];
__device__ __nv_bfloat16 g_W1lo[(size_t)DIM * DIM];
__device__ __nv_bfloat16 g_W2hi[(size_t)DIM * DIM];
__device__ __nv_bfloat16 g_W2lo[(size_t)DIM * DIM];
__device__ float g_dirs[3 * DIM];
__device__ float g_coef[(size_t)BATCH * 4];

// ---------------- PTX helpers -------------------------------------------------
__device__ __forceinline__ uint32_t smem_u32(const void* p) {
    uint32_t a;
    asm("{ .reg .u64 t; cvta.to.shared.u64 t, %1; cvt.u32.u64 %0, t; }" : "=r"(a) : "l"(p));
    return a;
}

#if HAS_TCGEN05
#define TCGEN05_ALLOC(sm, n) \
    asm volatile("tcgen05.alloc.cta_group::1.sync.aligned.shared::cta.b32 [%0], %1;" :: "r"(sm), "r"(n) : "memory")
#define TCGEN05_RELINQ() \
    asm volatile("tcgen05.relinquish_alloc_permit.cta_group::1.sync.aligned;")
#define TCGEN05_DEALLOC(t, n) \
    asm volatile("tcgen05.dealloc.cta_group::1.sync.aligned.b32 %0, %1;" :: "r"(t), "r"(n))
#define TCGEN05_COMMIT(mb) \
    asm volatile("tcgen05.commit.cta_group::1.mbarrier::arrive::one.shared::cluster.b64 [%0];" :: "r"(mb) : "memory")
#define TCGEN05_FENCE_AFTER() asm volatile("tcgen05.fence::after_thread_sync;" ::: "memory")
#define TCGEN05_WAIT_LD() asm volatile("tcgen05.wait::ld.sync.aligned;" ::: "memory")
#else
#define TCGEN05_ALLOC(sm, n)   ((void)0)
#define TCGEN05_RELINQ()       ((void)0)
#define TCGEN05_DEALLOC(t, n)  ((void)0)
#define TCGEN05_COMMIT(mb)     ((void)0)
#define TCGEN05_FENCE_AFTER()  ((void)0)
#define TCGEN05_WAIT_LD()      ((void)0)
#endif

#define MBARRIER_INIT(mb, c) \
    asm volatile("mbarrier.init.shared.b64 [%0], %1;" :: "r"(mb), "r"(c) : "memory")
#define MBARRIER_INVAL(mb) \
    asm volatile("mbarrier.inval.shared.b64 [%0];" :: "r"(mb) : "memory")
#define FENCE_PROXY_ASYNC() asm volatile("fence.proxy.async.shared::cta;" ::: "memory")
#define CP_ASYNC16(dst, src) \
    asm volatile("cp.async.cg.shared.global [%0], [%1], 16;" :: "r"(dst), "l"(src) : "memory")
#define CP_ASYNC_MBAR_ARRIVE(mb) \
    asm volatile("cp.async.mbarrier.arrive.noinc.shared::cta.b64 [%0];" :: "r"(mb) : "memory")
#define STS128(addr, a, b, c, d) \
    asm volatile("st.shared.v4.b32 [%0], {%1,%2,%3,%4};" :: "r"(addr), "r"(a), "r"(b), "r"(c), "r"(d) : "memory")
#define LDS128(a, b, c, d, addr) \
    asm volatile("ld.shared.v4.b32 {%0,%1,%2,%3}, [%4];" : "=r"(a), "=r"(b), "=r"(c), "=r"(d) : "r"(addr))

__device__ __forceinline__ void mbar_wait(uint32_t mb, uint32_t parity) {
    uint32_t done;
    asm volatile(
        "{\n\t.reg .pred p;\n\t"
        "mbarrier.try_wait.parity.acquire.cta.shared::cta.b64 p, [%1], %2;\n\t"
        "selp.b32 %0, 1, 0, p;\n\t}"
        : "=r"(done) : "r"(mb), "r"(parity) : "memory");
    if (!done) {
        asm volatile(
            "{\n\t.reg .pred P1;\n\t"
            "W_%=:\n\t"
            "mbarrier.try_wait.parity.acquire.cta.shared::cta.b64 P1, [%0], %1, 0x989680;\n\t"
            "@P1 bra.uni D_%=;\n\t"
            "bra.uni W_%=;\n\t"
            "D_%=:\n\t}"
            :: "r"(mb), "r"(parity) : "memory");
    }
}

__device__ __forceinline__ void tcgen05_ld32x32(uint32_t* r, uint32_t addr) {
#if HAS_TCGEN05
    asm volatile(
        "tcgen05.ld.sync.aligned.32x32b.x32.b32 "
        "{%0,%1,%2,%3,%4,%5,%6,%7,%8,%9,%10,%11,%12,%13,%14,%15,"
        "%16,%17,%18,%19,%20,%21,%22,%23,%24,%25,%26,%27,%28,%29,%30,%31}, [%32];"
        : "=r"(r[0]), "=r"(r[1]), "=r"(r[2]), "=r"(r[3]), "=r"(r[4]), "=r"(r[5]), "=r"(r[6]), "=r"(r[7]),
          "=r"(r[8]), "=r"(r[9]), "=r"(r[10]), "=r"(r[11]), "=r"(r[12]), "=r"(r[13]), "=r"(r[14]), "=r"(r[15]),
          "=r"(r[16]), "=r"(r[17]), "=r"(r[18]), "=r"(r[19]), "=r"(r[20]), "=r"(r[21]), "=r"(r[22]), "=r"(r[23]),
          "=r"(r[24]), "=r"(r[25]), "=r"(r[26]), "=r"(r[27]), "=r"(r[28]), "=r"(r[29]), "=r"(r[30]), "=r"(r[31])
        : "r"(addr));
#else
    for (int i = 0; i < 32; i++) r[i] = 0;
#endif
}

__device__ __forceinline__ void mma_bf16_ss(uint32_t d, uint64_t a, uint64_t b,
                                            uint32_t idesc, uint32_t acc) {
#if HAS_TCGEN05
    uint32_t z = 0;
    asm volatile(
        "{\n\t.reg .pred p;\n\tsetp.ne.u32 p, %5, 0;\n\t"
        "tcgen05.mma.cta_group::1.kind::f16 [%0], %1, %2, %3, {%4,%4,%4,%4}, p;\n\t}"
        :: "r"(d), "l"(a), "l"(b), "r"(idesc), "r"(z), "r"(acc) : "memory");
#endif
}

// SW64 swizzle (atom = 8 rows x 64 B) + descriptor  (proven correct R7/R10/R13)
__device__ __forceinline__ uint32_t swz64(uint32_t off) { return off ^ ((off >> 3) & 0x30); }
static constexpr uint64_t DESC_BASE_SW64 =
    (uint64_t(4) << 61) | (uint64_t(1) << 46) | (uint64_t(32) << 32) | (uint64_t(1) << 16);
__device__ __forceinline__ uint64_t mk_desc64(uint32_t addr) {
    return DESC_BASE_SW64 | ((uint64_t)(addr >> 4) & 0x3FFF);
}

// idesc: dtype=F32, atype=btype=BF16, M=128 (per MMA), N=256
#define MMA_IDESC ((1u << 4) | (1u << 7) | (1u << 10) | ((256u / 8) << 17) | ((128u / 16) << 24))

// ---------------- math helpers --------------------------------------------------
__device__ __forceinline__ float fast_tanh(float x) {
    float t = fabsf(x);
    float e = __expf(-2.f * t);
    float r = __fdividef(1.f - e, 1.f + e);
    return copysignf(r, x);
}
__device__ __forceinline__ void split_pack(float f0, float f1,
                                           uint32_t& H, uint32_t& L) {
    __nv_bfloat16 h0 = __float2bfloat16(f0);
    __nv_bfloat16 h1 = __float2bfloat16(f1);
    __nv_bfloat16 l0 = __float2bfloat16(f0 - __bfloat162float(h0));
    __nv_bfloat16 l1 = __float2bfloat16(f1 - __bfloat162float(h1));
    unsigned short uh0 = *(unsigned short*)&h0, uh1 = *(unsigned short*)&h1;
    unsigned short ul0 = *(unsigned short*)&l0, ul1 = *(unsigned short*)&l1;
    H = ((uint32_t)uh1 << 16) | uh0;
    L = ((uint32_t)ul1 << 16) | ul0;
}
__device__ __forceinline__ void unpack2(uint32_t w, float& a, float& b) {
    __nv_bfloat162 t = *(__nv_bfloat162*)&w;
    a = __bfloat162float(t.x);
    b = __bfloat162float(t.y);
}

// ---------------- cg1 tensor GEMM, 256x256 CTA tile, warp-specialized ---------
// R13/R15 structure (best known): cp.async producer warps, single MMA issuer,
// SMEM-transposed coalesced epilogue.
#define BMC 256
#define BN  256
#define KS  32
#define NIT (DIM / KS)                 // 64
#define NSTAGE 3
#define OP_BYTES (256 * 64)            // 16 KB
#define STAGE_BYTES (4 * OP_BYTES)     // 64 KB
#define SMEM_DATA 1024
#define SMEM_TOT (SMEM_DATA + NSTAGE * STAGE_BYTES)
#define MB_FULL(s) (sb + 16 + (s) * 8)
#define MB_DONE(s) (sb + 48 + (s) * 8)
#define NLOAD 128

__device__ __forceinline__ void load_op256_w(uint32_t dst, const __nv_bfloat16* g,
                                             int k0, int ltid) {
#pragma unroll
    for (int i = 0; i < 8; i++) {
        int idx = i * NLOAD + ltid;
        int r = idx >> 2;
        int c = idx & 3;
        CP_ASYNC16(dst + swz64((uint32_t)(r * 64 + c * 16)),
                   g + (size_t)r * DIM + k0 + c * 8);
    }
}

__device__ __forceinline__ void load_stage_w(
    uint32_t sbase, int s, int k0,
    const __nv_bfloat16* Ah, const __nv_bfloat16* Al,
    const __nv_bfloat16* Bh, const __nv_bfloat16* Bl, int ltid) {
    uint32_t st = sbase + SMEM_DATA + s * STAGE_BYTES;
    load_op256_w(st, Ah, k0, ltid);
    load_op256_w(st + OP_BYTES, Al, k0, ltid);
    load_op256_w(st + 2 * OP_BYTES, Bh, k0, ltid);
    load_op256_w(st + 3 * OP_BYTES, Bl, k0, ltid);
}

// EPI 0: tanh(acc + bias) -> Ohi/Olo.   EPI 1: acc + bias -> Ohi/Olo (delta).
template <int EPI>
__global__ void __launch_bounds__(256, 1)
gemm_tc(const __nv_bfloat16* __restrict__ Ahi, const __nv_bfloat16* __restrict__ Alo,
        const __nv_bfloat16* __restrict__ Bhi, const __nv_bfloat16* __restrict__ Blo,
        const float* __restrict__ bias,
        __nv_bfloat16* __restrict__ Ohi, __nv_bfloat16* __restrict__ Olo) {
    extern __shared__ char smem[];
    uint32_t sb = smem_u32(smem);
    const int tid = threadIdx.x;
    const int wid = tid >> 5;
    const int lid = tid & 31;
    const int bm = blockIdx.y * BMC;
    const int bn = blockIdx.x * BN;

    if (wid == 0) TCGEN05_ALLOC(sb, 512);
    if (tid == 0) {
#pragma unroll
        for (int s = 0; s < NSTAGE; s++) {
            MBARRIER_INIT(MB_FULL(s), NLOAD);
            MBARRIER_INIT(MB_DONE(s), 1);
        }
    }
    __syncthreads();
    uint32_t tmem;
    asm volatile("ld.shared.b32 %0, [%1];" : "=r"(tmem) : "r"(sb));
    if (wid == 0) TCGEN05_RELINQ();
    __syncthreads();

    const __nv_bfloat16* Ah = Ahi + (size_t)bm * DIM;
    const __nv_bfloat16* Al = Alo + (size_t)bm * DIM;
    const __nv_bfloat16* Bh = Bhi + (size_t)bn * DIM;
    const __nv_bfloat16* Bl = Blo + (size_t)bn * DIM;

    if (tid >= 128) {
        const int ltid = tid - 128;
#pragma unroll
        for (int s = 0; s < NSTAGE; s++) {
            load_stage_w(sb, s, s * KS, Ah, Al, Bh, Bl, ltid);
            CP_ASYNC_MBAR_ARRIVE(MB_FULL(s));
        }
        for (int it = 0; it + NSTAGE < NIT; it++) {
            const int s = it % NSTAGE;
            const uint32_t ph = (uint32_t)(it / NSTAGE) & 1u;
            mbar_wait(MB_DONE(s), ph);
            load_stage_w(sb, s, (it + NSTAGE) * KS, Ah, Al, Bh, Bl, ltid);
            CP_ASYNC_MBAR_ARRIVE(MB_FULL(s));
        }
        // loaders are phase-exact on done[]; only they take the final wait (R9 lesson)
        mbar_wait(MB_DONE((NIT - 1) % NSTAGE), (uint32_t)((NIT - 1) / NSTAGE) & 1u);
    } else if (tid == 0) {
        for (int it = 0; it < NIT; it++) {
            const int s = it % NSTAGE;
            const uint32_t ph = (uint32_t)(it / NSTAGE) & 1u;
            mbar_wait(MB_FULL(s), ph);
            FENCE_PROXY_ASYNC();
            uint32_t st = sb + SMEM_DATA + s * STAGE_BYTES;
            uint64_t dAh = mk_desc64(st);
            uint64_t dAl = mk_desc64(st + OP_BYTES);
            uint64_t dBh = mk_desc64(st + 2 * OP_BYTES);
            uint64_t dBl = mk_desc64(st + 3 * OP_BYTES);
#pragma unroll
            for (int j = 0; j < 2; j++) {
#pragma unroll
                for (int m = 0; m < 2; m++) {
                    uint64_t aoff = (uint64_t)(m * 512 + j * 2);
                    uint32_t d = tmem + m * 256;
                    mma_bf16_ss(d, dAh + aoff, dBh + j * 2, MMA_IDESC, !(it == 0 && j == 0));
                    mma_bf16_ss(d, dAh + aoff, dBl + j * 2, MMA_IDESC, 1u);
                    mma_bf16_ss(d, dAl + aoff, dBh + j * 2, MMA_IDESC, 1u);
                }
            }
            TCGEN05_COMMIT(MB_DONE(s));
        }
    }

    __syncthreads();          // releases everyone after loaders saw final commit
    TCGEN05_FENCE_AFTER();

    // ---- transposed epilogue: TMEM -> SMEM tile -> coalesced STG ----
    const uint32_t SH_H = sb + SMEM_DATA;
    const uint32_t SH_L = SH_H + 128 * 512;
    for (int a = 0; a < 2; a++) {   // M-halves
        const int mlane = (wid & 3) * 32 + lid;      // TMEM lane = row in half
        const int colh = (wid >> 2) * 128;           // col range of this warp
        const uint32_t tb = tmem + a * 256 + colh;
        // phase 1: read TMEM cols, compute, store swizzled into SMEM
#pragma unroll
        for (int cb = 0; cb < 128; cb += 32) {
            uint32_t r[32];
            tcgen05_ld32x32(r, tb + cb);
            TCGEN05_WAIT_LD();
#pragma unroll
            for (int c = 0; c < 32; c += 8) {
                uint32_t H[4], L[4];
#pragma unroll
                for (int k = 0; k < 4; k++) {
                    int n = bn + colh + cb + c + k * 2;
                    float f0 = __uint_as_float(r[c + k * 2]) + bias[n];
                    float f1 = __uint_as_float(r[c + k * 2 + 1]) + bias[n + 1];
                    if (EPI == 0) { f0 = fast_tanh(f0); f1 = fast_tanh(f1); }
                    split_pack(f0, f1, H[k], L[k]);
                }
                uint32_t colbyte = (uint32_t)(colh + cb + c) * 2;
                uint32_t off = (uint32_t)mlane * 512 + (colbyte ^ (((uint32_t)mlane & 7) << 4));
                STS128(SH_H + off, H[0], H[1], H[2], H[3]);
                STS128(SH_L + off, L[0], L[1], L[2], L[3]);
            }
        }
        __syncthreads();
        // phase 2: coalesced 128B-line stores
#pragma unroll
        for (int g = 0; g < 4; g++) {
            int row = wid * 16 + g * 4 + (lid >> 3);
            size_t gbase = ((size_t)(bm + a * 128 + row) * DIM + bn) * 2;
#pragma unroll
            for (int ln = 0; ln < 4; ln++) {
                uint32_t cbyte = (uint32_t)(ln * 128 + (lid & 7) * 16);
                uint32_t src = (uint32_t)row * 512 + (cbyte ^ (((uint32_t)row & 7) << 4));
                uint32_t h0, h1, h2, h3, l0, l1, l2, l3;
                LDS128(h0, h1, h2, h3, SH_H + src);
                LDS128(l0, l1, l2, l3, SH_L + src);
                *(uint4*)((char*)Ohi + gbase + cbyte) = make_uint4(h0, h1, h2, h3);
                *(uint4*)((char*)Olo + gbase + cbyte) = make_uint4(l0, l1, l2, l3);
            }
        }
        __syncthreads();
    }

    if (tid == 0) {
#pragma unroll
        for (int s = 0; s < NSTAGE; s++) { MBARRIER_INVAL(MB_FULL(s)); MBARRIER_INVAL(MB_DONE(s)); }
    }
    __syncthreads();
    if (wid == 0) TCGEN05_DEALLOC(tmem, 512);
}

// ---------------- block reduction of 4 sums ----------------------------------
__device__ __forceinline__ float4 block_reduce4(float4 v) {
    __shared__ float4 sh[8];
    int lane = threadIdx.x & 31;
    int w = threadIdx.x >> 5;
#pragma unroll
    for (int o = 16; o; o >>= 1) {
        v.x += __shfl_xor_sync(0xffffffffu, v.x, o);
        v.y += __shfl_xor_sync(0xffffffffu, v.y, o);
        v.z += __shfl_xor_sync(0xffffffffu, v.z, o);
        v.w += __shfl_xor_sync(0xffffffffu, v.w, o);
    }
    if (lane == 0) sh[w] = v;
    __syncthreads();
    if (w == 0) {
        float4 t = (lane < 8) ? sh[lane] : make_float4(0.f, 0.f, 0.f, 0.f);
#pragma unroll
        for (int o = 4; o; o >>= 1) {
            t.x += __shfl_xor_sync(0xffffffffu, t.x, o);
            t.y += __shfl_xor_sync(0xffffffffu, t.y, o);
            t.z += __shfl_xor_sync(0xffffffffu, t.z, o);
            t.w += __shfl_xor_sync(0xffffffffu, t.w, o);
        }
        if (lane == 0) sh[0] = t;
    }
    __syncthreads();
    return sh[0];
}

__device__ __forceinline__ void write_coefs(int row, float nh2,
                                            float de, float dc, float dn) {
    float nh = sqrtf(nh2);
    float inv = 1.f / fmaxf(nh, 1e-12f);
    float dots[3] = {de, dc, dn};
#pragma unroll
    for (int k = 0; k < 3; k++) {
        float a = dots[k] * inv;
        float r = sqrtf(fmaxf(nh2 - 2.f * dots[k] + 1.f, 0.f));
        g_coef[(size_t)row * 4 + k] = kS[k] * (DIVC - a) / fmaxf(r, 1e-12f);
    }
}

// ---------------- small prep kernels ------------------------------------------
__global__ void prep_dirs_kernel(const float* __restrict__ e,
                                 const float* __restrict__ c,
                                 const float* __restrict__ n) {
    const float* src = (blockIdx.x == 0) ? e : (blockIdx.x == 1 ? c : n);
    float4 s = make_float4(0.f, 0.f, 0.f, 0.f);
    for (int i = threadIdx.x; i < DIM; i += 256) {
        float v = src[i];
        s.x += v * v;
    }
    s = block_reduce4(s);
    float inv = 1.f / fmaxf(sqrtf(s.x), 1e-12f);
    for (int i = threadIdx.x; i < DIM; i += 256)
        g_dirs[blockIdx.x * DIM + i] = src[i] * inv;
}

// fused: split h0 into hi/lo + layer-0 stats/coefs (float4 loads, uint2 stores)
__global__ void init_kernel(const float* __restrict__ h0,
                            __nv_bfloat16* __restrict__ hhi,
                            __nv_bfloat16* __restrict__ hlo) {
    int row = blockIdx.x;
    int t = threadIdx.x;
    const float4* hr = (const float4*)(h0 + (size_t)row * DIM);
    const float4* de = (const float4*)g_dirs;
    const float4* dc = (const float4*)(g_dirs + DIM);
    const float4* dn = (const float4*)(g_dirs + 2 * DIM);
    uint2* Hh = (uint2*)(g_hhi + (size_t)row * DIM);
    uint2* Hl = (uint2*)(g_hlo + (size_t)row * DIM);
    float4 s = make_float4(0.f, 0.f, 0.f, 0.f);
#pragma unroll
    for (int j = 0; j < 2; j++) {
        int q = t + j * 256;            // float4 index (DIM/4 = 512)
        float4 v = hr[q];
        float4 e = de[q], c = dc[q], n = dn[q];
        s.x = fmaf(v.x, v.x, s.x); s.x = fmaf(v.y, v.y, s.x);
        s.x = fmaf(v.z, v.z, s.x); s.x = fmaf(v.w, v.w, s.x);
        s.y = fmaf(v.x, e.x, s.y); s.y = fmaf(v.y, e.y, s.y);
        s.y = fmaf(v.z, e.z, s.y); s.y = fmaf(v.w, e.w, s.y);
        s.z = fmaf(v.x, c.x, s.z); s.z = fmaf(v.y, c.y, s.z);
        s.z = fmaf(v.z, c.z, s.z); s.z = fmaf(v.w, c.w, s.z);
        s.w = fmaf(v.x, n.x, s.w); s.w = fmaf(v.y, n.y, s.w);
        s.w = fmaf(v.z, n.z, s.w); s.w = fmaf(v.w, n.w, s.w);
        uint2 H, L;
        split_pack(v.x, v.y, H.x, L.x);
        split_pack(v.z, v.w, H.y, L.y);
        Hh[q] = H;
        Hl[q] = L;
    }
    s = block_reduce4(s);
    if (t == 0) write_coefs(row, s.x, s.y, s.z, s.w);
}

// weight split: float4 loads (4 floats = 2 packed words), uint2 stores
__global__ void conv_split_kernel(const float* __restrict__ src,
                                  __nv_bfloat16* __restrict__ hi,
                                  __nv_bfloat16* __restrict__ lo, size_t nquad) {
    size_t q = (size_t)blockIdx.x * blockDim.x + threadIdx.x;
    if (q < nquad) {
        float4 v = ((const float4*)src)[q];
        uint2 H, L;
        split_pack(v.x, v.y, H.x, L.x);
        split_pack(v.z, v.w, H.y, L.y);
        ((uint2*)hi)[q] = H;
        ((uint2*)lo)[q] = L;
    }
}

// ---------------- fused update + cap + stats + split (uint2/float4 vectorized) -
__global__ void update_kernel(__nv_bfloat16* __restrict__ hhi,
                              __nv_bfloat16* __restrict__ hlo,
                              const __nv_bfloat16* __restrict__ Dhi,
                              const __nv_bfloat16* __restrict__ Dlo,
                              float* __restrict__ hout, int write_f32) {
    int row = blockIdx.x;
    int t = threadIdx.x;
    const uint2* Hh = (const uint2*)(hhi + (size_t)row * DIM);
    const uint2* Hl = (const uint2*)(hlo + (size_t)row * DIM);
    const uint2* Dh = (const uint2*)(Dhi + (size_t)row * DIM);
    const uint2* Dl = (const uint2*)(Dlo + (size_t)row * DIM);
    const float4* de = (const float4*)g_dirs;
    const float4* dc = (const float4*)(g_dirs + DIM);
    const float4* dn = (const float4*)(g_dirs + 2 * DIM);

    float ce = g_coef[(size_t)row * 4 + 0];
    float cc = g_coef[(size_t)row * 4 + 1];
    float cn = g_coef[(size_t)row * 4 + 2];
    float keep = 1.f - (ce + cc + cn);

    float4 x[2];
    float4 s = make_float4(0.f, 0.f, 0.f, 0.f);
#pragma unroll
    for (int j = 0; j < 2; j++) {
        int q = t + j * 256;            // uint2 / float4 index (512 total)
        uint2 hw = Hh[q], lw = Hl[q], dw = Dh[q], ew2 = Dl[q];
        float h0, h1, h2, h3, hl0, hl1, hl2, hl3;
        float d0, d1, d2, d3, dl0, dl1, dl2, dl3;
        unpack2(hw.x, h0, h1);  unpack2(hw.y, h2, h3);
        unpack2(lw.x, hl0, hl1); unpack2(lw.y, hl2, hl3);
        unpack2(dw.x, d0, d1);  unpack2(dw.y, d2, d3);
        unpack2(ew2.x, dl0, dl1); unpack2(ew2.y, dl2, dl3);
        float4 e = de[q], c = dc[q], n = dn[q];
        float v0 = fmaf(h0 + hl0, keep, d0 + dl0) + ce * e.x + cc * c.x + cn * n.x;
        float v1 = fmaf(h1 + hl1, keep, d1 + dl1) + ce * e.y + cc * c.y + cn * n.y;
        float v2 = fmaf(h2 + hl2, keep, d2 + dl2) + ce * e.z + cc * c.z + cn * n.z;
        float v3 = fmaf(h3 + hl3, keep, d3 + dl3) + ce * e.w + cc * c.w + cn * n.w;
        x[j] = make_float4(v0, v1, v2, v3);
        s.x = fmaf(v0, v0, s.x); s.x = fmaf(v1, v1, s.x);
        s.x = fmaf(v2, v2, s.x); s.x = fmaf(v3, v3, s.x);
        s.y = fmaf(v0, e.x, s.y); s.y = fmaf(v1, e.y, s.y);
        s.y = fmaf(v2, e.z, s.y); s.y = fmaf(v3, e.w, s.y);
        s.z = fmaf(v0, c.x, s.z); s.z = fmaf(v1, c.y, s.z);
        s.z = fmaf(v2, c.z, s.z); s.z = fmaf(v3, c.w, s.z);
        s.w = fmaf(v0, n.x, s.w); s.w = fmaf(v1, n.y, s.w);
        s.w = fmaf(v2, n.z, s.w); s.w = fmaf(v3, n.w, s.w);
    }
    s = block_reduce4(s);
    float norm = sqrtf(s.x);
    float sc = (norm > CAPV) ? (CAPV / (norm + 1e-8f)) : 1.f;
    if (write_f32) {
        float4* out = (float4*)(hout + (size_t)row * DIM);
#pragma unroll
        for (int j = 0; j < 2; j++) {
            int q = t + j * 256;
            out[q] = make_float4(x[j].x * sc, x[j].y * sc, x[j].z * sc, x[j].w * sc);
        }
    } else {
        uint2* Wh = (uint2*)(hhi + (size_t)row * DIM);
        uint2* Wl = (uint2*)(hlo + (size_t)row * DIM);
#pragma unroll
        for (int j = 0; j < 2; j++) {
            int q = t + j * 256;
            uint2 H, L;
            split_pack(x[j].x * sc, x[j].y * sc, H.x, L.x);
            split_pack(x[j].z * sc, x[j].w * sc, H.y, L.y);
            Wh[q] = H;
            Wl[q] = L;
        }
        if (t == 0)
            write_coefs(row, sc * sc * s.x, sc * s.y, sc * s.z, sc * s.w);
    }
}

// ---------------- launch --------------------------------------------------------
extern "C" void kernel_launch(void* const* d_in, const int* in_sizes, int n_in,
                              void* d_out, int out_size) {
    const float* h0 = (const float*)d_in[0];
    const float* ae = (const float*)d_in[1];
    const float* ac = (const float*)d_in[2];
    const float* an = (const float*)d_in[3];
    const float* W1 = (const float*)d_in[4];
    const float* b1 = (const float*)d_in[5];
    const float* W2 = (const float*)d_in[6];
    const float* b2 = (const float*)d_in[7];
    float* h = (float*)d_out;

    __nv_bfloat16 *hhi, *hlo, *Thi, *Tlo, *Dhi, *Dlo, *W1h, *W1l, *W2h, *W2l;
    cudaGetSymbolAddress((void**)&hhi, g_hhi);
    cudaGetSymbolAddress((void**)&hlo, g_hlo);
    cudaGetSymbolAddress((void**)&Thi, g_Thi);
    cudaGetSymbolAddress((void**)&Tlo, g_Tlo);
    cudaGetSymbolAddress((void**)&Dhi, g_Dhi);
    cudaGetSymbolAddress((void**)&Dlo, g_Dlo);
    cudaGetSymbolAddress((void**)&W1h, g_W1hi);
    cudaGetSymbolAddress((void**)&W1l, g_W1lo);
    cudaGetSymbolAddress((void**)&W2h, g_W2hi);
    cudaGetSymbolAddress((void**)&W2l, g_W2lo);

    cudaFuncSetAttribute(gemm_tc<0>, cudaFuncAttributeMaxDynamicSharedMemorySize, SMEM_TOT);
    cudaFuncSetAttribute(gemm_tc<1>, cudaFuncAttributeMaxDynamicSharedMemorySize, SMEM_TOT);

    size_t nq = (size_t)DIM * DIM / 4;
    conv_split_kernel<<<(unsigned)((nq + 511) / 512), 512>>>(W1, W1h, W1l, nq);
    conv_split_kernel<<<(unsigned)((nq + 511) / 512), 512>>>(W2, W2h, W2l, nq);
    prep_dirs_kernel<<<3, 256>>>(ae, ac, an);
    init_kernel<<<BATCH, 256>>>(h0, hhi, hlo);

    dim3 ggrid(DIM / BN, BATCH / BMC);   // (8, 64) = 512 CTAs
    for (int l = 0; l < NLAYERS; l++) {
        gemm_tc<0><<<ggrid, 256, SMEM_TOT>>>(hhi, hlo, W1h, W1l, b1, Thi, Tlo);
        gemm_tc<1><<<ggrid, 256, SMEM_TOT>>>(Thi, Tlo, W2h, W2l, b2, Dhi, Dlo);
        update_kernel<<<BATCH, 256>>>(hhi, hlo, Dhi, Dlo, h, l == NLAYERS - 1);
    }
}